// round 9
// baseline (speedup 1.0000x reference)
#include <cuda_runtime.h>

// out[i] = sum_b sum_j x1[b,j] * x2[b,(i-j) mod 1024]
// Per-CTA: Z = FFT(x1 + i*x2) [radix-4 Stockham]; P = X1.*X2; y_b = Re IDFT(P).
// R9: NO grid barrier. y_b quantized to fixed point (2^24) and accumulated with
// deterministic integer REDG atomics; the last-arriving CTA alone converts to
// fp32 and resets state for the next graph replay.

#define BSZ 128
#define D   1024
#define DMASK 1023
#define FXSCALE 16777216.0f          // 2^24
#define FXINV   (1.0f / 16777216.0f)

__device__ unsigned long long g_acc[D];   // fixed-point accumulator (zero-init)
__device__ unsigned g_done = 0;           // completion counter (zero-init)

__device__ __forceinline__ float2 cmul(float2 a, float2 w) {
    return make_float2(a.x * w.x - a.y * w.y, a.x * w.y + a.y * w.x);
}
__device__ __forceinline__ float2 cmulc(float2 a, float2 w) {
    return make_float2(a.x * w.x + a.y * w.y, a.y * w.x - a.x * w.y);
}
__device__ __forceinline__ float2 cadd(float2 a, float2 b) { return make_float2(a.x + b.x, a.y + b.y); }
__device__ __forceinline__ float2 csub(float2 a, float2 b) { return make_float2(a.x - b.x, a.y - b.y); }

// One radix-4 Stockham stage (= fused radix-2 stages p, p+1). 256 threads.
template <bool INV>
__device__ __forceinline__ void r4_step(const float2* __restrict__ src,
                                        float2* __restrict__ dst,
                                        const float2* __restrict__ roots,
                                        int p, int tid) {
    const int Ns = 1 << p;
    const int k  = tid & (Ns - 1);
    const int g2 = tid >> p;

    const float2 s0 = src[tid];
    const float2 s1 = src[tid + 256];
    const float2 s2 = src[tid + 512];
    const float2 s3 = src[tid + 768];

    const float2 w = roots[k << (9 - p)];
    const float2 v = roots[k << (8 - p)];

    const float2 m2 = INV ? cmul(s2, w) : cmulc(s2, w);
    const float2 m3 = INV ? cmul(s3, w) : cmulc(s3, w);
    const float2 t0 = cadd(s0, m2), t1 = csub(s0, m2);
    const float2 t2 = cadd(s1, m3), t3 = csub(s1, m3);

    const float2 a2 = INV ? cmul(t2, v) : cmulc(t2, v);
    const float2 x  = INV ? cmul(t3, v) : cmulc(t3, v);
    const float2 jx = INV ? make_float2(-x.y, x.x)    // +i*x
                          : make_float2(x.y, -x.x);   // -i*x

    const int o = g2 * 4 * Ns + k;
    dst[o]          = cadd(t0, a2);
    dst[o + Ns]     = cadd(t1, jx);
    dst[o + 2 * Ns] = csub(t0, a2);
    dst[o + 3 * Ns] = csub(t1, jx);
}

__global__ void __launch_bounds__(256, 1)
fftconv3_kernel(const float* __restrict__ x1, const float* __restrict__ x2,
                float* __restrict__ out) {
    __shared__ float2 bufA[D];
    __shared__ float2 bufB[D];
    __shared__ float2 roots[D];   // roots[m] = e^{+2*pi*i*m/1024}
    __shared__ unsigned s_last;

    const int b   = blockIdx.x;
    const int tid = threadIdx.x;

    // ---- root table ----
    #pragma unroll
    for (int m = tid; m < D; m += 256) {
        const float mm = (m >= D / 2) ? (float)(m - D) : (float)m;
        float s, c;
        __sincosf(6.283185307179586f * (mm * (1.0f / D)), &s, &c);
        roots[m] = make_float2(c, s);
    }

    // ---- load & pack z = x1 + i*x2 ----
    {
        const float4 v1 = reinterpret_cast<const float4*>(x1 + b * D)[tid];
        const float4 v2 = reinterpret_cast<const float4*>(x2 + b * D)[tid];
        bufA[4 * tid + 0] = make_float2(v1.x, v2.x);
        bufA[4 * tid + 1] = make_float2(v1.y, v2.y);
        bufA[4 * tid + 2] = make_float2(v1.z, v2.z);
        bufA[4 * tid + 3] = make_float2(v1.w, v2.w);
    }
    __syncthreads();

    // ---- forward FFT: 5 radix-4 stages ----
    r4_step<false>(bufA, bufB, roots, 0, tid); __syncthreads();
    r4_step<false>(bufB, bufA, roots, 2, tid); __syncthreads();
    r4_step<false>(bufA, bufB, roots, 4, tid); __syncthreads();
    r4_step<false>(bufB, bufA, roots, 6, tid); __syncthreads();
    r4_step<false>(bufA, bufB, roots, 8, tid); __syncthreads();
    // DFT (natural order) in bufB

    // ---- unpack & pointwise product -> bufA ----
    #pragma unroll
    for (int u = 0; u < 4; u++) {
        const int k = tid + u * 256;
        const float2 zk = bufB[k];
        const float2 zm = bufB[(D - k) & DMASK];
        const float a = zk.x, bb = zk.y, c = zm.x, d = zm.y;
        const float x1r = a + c,  x1i = bb - d;
        const float x2r = bb + d, x2i = c - a;
        bufA[k] = make_float2(0.25f * (x1r * x2r - x1i * x2i),
                              0.25f * (x1r * x2i + x1i * x2r));
    }
    __syncthreads();

    // ---- inverse FFT ----
    r4_step<true>(bufA, bufB, roots, 0, tid); __syncthreads();
    r4_step<true>(bufB, bufA, roots, 2, tid); __syncthreads();
    r4_step<true>(bufA, bufB, roots, 4, tid); __syncthreads();
    r4_step<true>(bufB, bufA, roots, 6, tid); __syncthreads();
    r4_step<true>(bufA, bufB, roots, 8, tid); __syncthreads();
    // unnormalized IDFT in bufB; y_b[n] = bufB[n].x / 1024

    // ---- deterministic fixed-point accumulation (order-independent) ----
    #pragma unroll
    for (int u = 0; u < 4; u++) {
        const int n = tid + u * 256;
        const float y = bufB[n].x * (1.0f / D);
        const long long q = llrintf(y * FXSCALE);
        atomicAdd(&g_acc[n], (unsigned long long)q);
    }

    // ---- completion: only the LAST CTA converts & resets ----
    __syncthreads();
    if (tid == 0) {
        __threadfence();  // make this CTA's atomics globally visible first
        s_last = (atomicAdd(&g_done, 1u) == BSZ - 1) ? 1u : 0u;
    }
    __syncthreads();

    if (s_last) {
        #pragma unroll
        for (int u = 0; u < 4; u++) {
            const int i = tid + u * 256;
            unsigned long long v;
            asm volatile("ld.global.acquire.gpu.u64 %0, [%1];"
                         : "=l"(v) : "l"(&g_acc[i]));
            out[i] = (float)(long long)v * FXINV;
            g_acc[i] = 0ull;  // reset for next graph replay
        }
        if (tid == 0) g_done = 0;
    }
}

extern "C" void kernel_launch(void* const* d_in, const int* in_sizes, int n_in,
                              void* d_out, int out_size) {
    const float* x1  = (const float*)d_in[0];  // (128, 1024) fp32
    const float* x2  = (const float*)d_in[1];  // (128, 1024) fp32
    float*       out = (float*)d_out;          // (1,1,1024) fp32

    fftconv3_kernel<<<BSZ, 256>>>(x1, x2, out);
}

// round 10
// speedup vs baseline: 1.2647x; 1.2647x over previous
#include <cuda_runtime.h>

// out[i] = sum_b sum_j x1[b,j] * x2[b,(i-j) mod 1024]
// Per-CTA: Z = FFT(x1 + i*x2) [radix-4 Stockham]; P = X1.*X2; y_b = Re IDFT(P).
// R10: fuse global-load into fwd stage0, unpack+product into inv stage0,
// global-store into inv stage4 (all twiddle-free seams). 9 BARs instead of 14.
// One ticket barrier + distributed reduction (proven R5/R8 epilogue).

#define BSZ 128
#define D   1024
#define DMASK 1023

__device__ float    g_partial[BSZ * D];
__device__ unsigned g_counter = 0;

__device__ __forceinline__ float2 cmul(float2 a, float2 w) {
    return make_float2(a.x * w.x - a.y * w.y, a.x * w.y + a.y * w.x);
}
__device__ __forceinline__ float2 cmulc(float2 a, float2 w) {
    return make_float2(a.x * w.x + a.y * w.y, a.y * w.x - a.x * w.y);
}
__device__ __forceinline__ float2 cadd(float2 a, float2 b) { return make_float2(a.x + b.x, a.y + b.y); }
__device__ __forceinline__ float2 csub(float2 a, float2 b) { return make_float2(a.x - b.x, a.y - b.y); }

// One radix-4 Stockham stage (middle stages, p in {2,4,6,8}). 256 threads.
template <bool INV>
__device__ __forceinline__ void r4_step(const float2* __restrict__ src,
                                        float2* __restrict__ dst,
                                        const float2* __restrict__ roots,
                                        int p, int tid) {
    const int Ns = 1 << p;
    const int k  = tid & (Ns - 1);
    const int g2 = tid >> p;

    const float2 s0 = src[tid];
    const float2 s1 = src[tid + 256];
    const float2 s2 = src[tid + 512];
    const float2 s3 = src[tid + 768];

    const float2 w = roots[k << (9 - p)];
    const float2 v = roots[k << (8 - p)];

    const float2 m2 = INV ? cmul(s2, w) : cmulc(s2, w);
    const float2 m3 = INV ? cmul(s3, w) : cmulc(s3, w);
    const float2 t0 = cadd(s0, m2), t1 = csub(s0, m2);
    const float2 t2 = cadd(s1, m3), t3 = csub(s1, m3);

    const float2 a2 = INV ? cmul(t2, v) : cmulc(t2, v);
    const float2 x  = INV ? cmul(t3, v) : cmulc(t3, v);
    const float2 jx = INV ? make_float2(-x.y, x.x)    // +i*x
                          : make_float2(x.y, -x.x);   // -i*x

    const int o = g2 * 4 * Ns + k;
    dst[o]          = cadd(t0, a2);
    dst[o + Ns]     = cadd(t1, jx);
    dst[o + 2 * Ns] = csub(t0, a2);
    dst[o + 3 * Ns] = csub(t1, jx);
}

// Spectrum unpack + pointwise product: P[j] from Z[j], Z[(D-j)%D].
__device__ __forceinline__ float2 spec_prod(float2 zk, float2 zm) {
    const float a = zk.x, bb = zk.y, c = zm.x, d = zm.y;
    const float x1r = a + c,  x1i = bb - d;
    const float x2r = bb + d, x2i = c - a;
    return make_float2(0.25f * (x1r * x2r - x1i * x2i),
                       0.25f * (x1r * x2i + x1i * x2r));
}

__global__ void __launch_bounds__(256, 1)
fftconv4_kernel(const float* __restrict__ x1, const float* __restrict__ x2,
                float* __restrict__ out) {
    __shared__ float2 bufA[D];
    __shared__ float2 bufB[D];
    __shared__ float2 roots[D];   // roots[m] = e^{+2*pi*i*m/1024}
    __shared__ float  red[256];

    const int b   = blockIdx.x;
    const int tid = threadIdx.x;

    // ---- issue global loads FIRST (overlap DRAM latency with root build) ----
    const float* p1 = x1 + b * D + tid;
    const float* p2 = x2 + b * D + tid;
    const float a0 = p1[0], a1 = p1[256], a2i = p1[512], a3 = p1[768];
    const float c0 = p2[0], c1 = p2[256], c2  = p2[512], c3 = p2[768];

    // ---- root table ----
    #pragma unroll
    for (int m = tid; m < D; m += 256) {
        const float mm = (m >= D / 2) ? (float)(m - D) : (float)m;
        float s, c;
        __sincosf(6.283185307179586f * (mm * (1.0f / D)), &s, &c);
        roots[m] = make_float2(c, s);
    }

    // ---- fwd stage p=0 fused with load (all twiddles = 1): regs -> bufA ----
    {
        const float2 s0 = make_float2(a0, c0);
        const float2 s1 = make_float2(a1, c1);
        const float2 s2 = make_float2(a2i, c2);
        const float2 s3 = make_float2(a3, c3);
        const float2 t0 = cadd(s0, s2), t1 = csub(s0, s2);
        const float2 t2 = cadd(s1, s3), t3 = csub(s1, s3);
        const float2 jx = make_float2(t3.y, -t3.x);   // -i*t3 (forward)
        const int o = 4 * tid;
        bufA[o]     = cadd(t0, t2);
        bufA[o + 1] = cadd(t1, jx);
        bufA[o + 2] = csub(t0, t2);
        bufA[o + 3] = csub(t1, jx);
    }
    __syncthreads();  // also covers roots visibility

    // ---- fwd stages p=2,4,6,8: A->B->A->B->A ----
    r4_step<false>(bufA, bufB, roots, 2, tid); __syncthreads();
    r4_step<false>(bufB, bufA, roots, 4, tid); __syncthreads();
    r4_step<false>(bufA, bufB, roots, 6, tid); __syncthreads();
    r4_step<false>(bufB, bufA, roots, 8, tid); __syncthreads();
    // forward DFT (natural order) in bufA

    // ---- inv stage p=0 fused with unpack+product (twiddles = 1): A -> B ----
    {
        const float2 s0 = spec_prod(bufA[tid],
                                    bufA[(D - tid) & DMASK]);
        const float2 s1 = spec_prod(bufA[tid + 256],
                                    bufA[(D - (tid + 256)) & DMASK]);
        const float2 s2 = spec_prod(bufA[tid + 512],
                                    bufA[(D - (tid + 512)) & DMASK]);
        const float2 s3 = spec_prod(bufA[tid + 768],
                                    bufA[(D - (tid + 768)) & DMASK]);
        const float2 t0 = cadd(s0, s2), t1 = csub(s0, s2);
        const float2 t2 = cadd(s1, s3), t3 = csub(s1, s3);
        const float2 jx = make_float2(-t3.y, t3.x);   // +i*t3 (inverse)
        const int o = 4 * tid;
        bufB[o]     = cadd(t0, t2);
        bufB[o + 1] = cadd(t1, jx);
        bufB[o + 2] = csub(t0, t2);
        bufB[o + 3] = csub(t1, jx);
    }
    __syncthreads();

    // ---- inv stages p=2,4,6: B->A->B->A ----
    r4_step<true>(bufB, bufA, roots, 2, tid); __syncthreads();
    r4_step<true>(bufA, bufB, roots, 4, tid); __syncthreads();
    r4_step<true>(bufB, bufA, roots, 6, tid); __syncthreads();

    // ---- inv stage p=8 fused with global store: A -> g_partial ----
    {
        const float2 s0 = bufA[tid];
        const float2 s1 = bufA[tid + 256];
        const float2 s2 = bufA[tid + 512];
        const float2 s3 = bufA[tid + 768];
        const float2 w  = roots[tid << 1];
        const float2 v  = roots[tid];
        const float2 m2 = cmul(s2, w);
        const float2 m3 = cmul(s3, w);
        const float2 t0 = cadd(s0, m2), t1 = csub(s0, m2);
        const float2 t2 = cadd(s1, m3), t3 = csub(s1, m3);
        const float2 av = cmul(t2, v);
        const float2 x  = cmul(t3, v);
        const float2 jx = make_float2(-x.y, x.x);     // +i*x
        float* gp = g_partial + b * D + tid;          // y real by construction
        gp[0]   = (t0.x + av.x) * (1.0f / D);
        gp[256] = (t1.x + jx.x) * (1.0f / D);
        gp[512] = (t0.x - av.x) * (1.0f / D);
        gp[768] = (t1.x - jx.x) * (1.0f / D);
    }

    // ---- single cross-CTA barrier (monotonic ticket, replay-safe) ----
    __syncthreads();
    if (tid == 0) {
        __threadfence();  // release g_partial writes
        const unsigned old    = atomicAdd(&g_counter, 1u);
        const unsigned target = old - (old & (BSZ - 1)) + BSZ;
        unsigned cur;
        do {
            asm volatile("ld.global.acquire.gpu.u32 %0, [%1];"
                         : "=r"(cur) : "l"(&g_counter));
        } while ((int)(cur - target) < 0);
    }
    __syncthreads();

    // ---- fused deterministic reduction: CTA c owns outputs [8c, 8c+8) ----
    {
        const int i    = blockIdx.x * 8 + (tid & 7);
        const int brow = tid >> 3;  // 0..31
        float s = __ldcg(&g_partial[(brow      ) * D + i])
                + __ldcg(&g_partial[(brow + 32 ) * D + i])
                + __ldcg(&g_partial[(brow + 64 ) * D + i])
                + __ldcg(&g_partial[(brow + 96 ) * D + i]);
        red[tid] = s;
        __syncthreads();
        if (tid < 8) {
            float t = 0.f;
            #pragma unroll
            for (int m = 0; m < 32; m++) t += red[tid + 8 * m];
            out[blockIdx.x * 8 + tid] = t;
        }
    }
}

extern "C" void kernel_launch(void* const* d_in, const int* in_sizes, int n_in,
                              void* d_out, int out_size) {
    const float* x1  = (const float*)d_in[0];  // (128, 1024) fp32
    const float* x2  = (const float*)d_in[1];  // (128, 1024) fp32
    float*       out = (float*)d_out;          // (1,1,1024) fp32

    fftconv4_kernel<<<BSZ, 256>>>(x1, x2, out);
}